// round 14
// baseline (speedup 1.0000x reference)
#include <cuda_runtime.h>
#include <cuda_fp16.h>

#define NN 50000
#define NE 800000
#define DIN 96
#define HID 128
#define NG 256
#define NNP 53248   // 52 * 1024, padded arrays for vectorized scan

// ---------------- scratch ----------------
__device__ __align__(16) int    g_deg[NNP];      // zero-init; re-zeroed by k_scan
__device__ __align__(16) int    g_off[NNP + 4];
__device__ __align__(16) int    g_cur[NNP];
__device__ __align__(16) int    g_gs[NG + 1];
__device__ __align__(16) int2   g_edge[NE];
__device__ __align__(16) __half g_Yr16[(size_t)NN * HID];
__device__ __align__(16) float  g_Yroot[(size_t)NN * HID];
__device__ __align__(16) float  g_u[HID];
__device__ __align__(16) float  g_v[HID];
__device__            float     g_c;
__device__ __align__(16) float  g_s[NN];
__device__ __align__(16) float  g_r[NN];

#define NB_COUNT ((NE + 255) / 256)   // 3125

// ---------------- fused: degree count + uv fold + graph bounds ----------------
__global__ void k_count_misc(const int* __restrict__ ei, const int* __restrict__ batch,
                             const float* __restrict__ Wr3, const float* __restrict__ Wro3,
                             const float* __restrict__ Wl, const float* __restrict__ b3) {
    int b = blockIdx.x;
    if (b < NB_COUNT) {
        int e = b * 256 + threadIdx.x;
        if (e < NE) atomicAdd(&g_deg[ei[NE + e]], 1);
    } else if (b == NB_COUNT) {
        int k = threadIdx.x;
        if (k < HID) {
            float su = 0.f, sv = 0.f;
            #pragma unroll 4
            for (int j = 0; j < HID; j++) {
                float wl = Wl[j];
                su = fmaf(wl, Wr3[j * HID + k], su);
                sv = fmaf(wl, Wro3[j * HID + k], sv);
            }
            g_u[k] = su;
            g_v[k] = sv;
            if (k == 0) {
                float c = 0.f;
                for (int j = 0; j < HID; j++) c = fmaf(Wl[j], b3[j], c);
                g_c = c;
            }
        }
    } else {
        int g = threadIdx.x;  // 0..255
        int lo = 0, hi = NN;
        while (lo < hi) {
            int m = (lo + hi) >> 1;
            if (batch[m] < g) lo = m + 1; else hi = m;
        }
        g_gs[g] = lo;
        if (g == 0) g_gs[NG] = NN;
    }
}

// ---------------- scan: vectorized, two-pass ----------------
__global__ __launch_bounds__(1024) void k_scan() {
    __shared__ int wsum[32];
    const int tid = threadIdx.x;
    const int base = tid * 52;
    const int4* dp = (const int4*)(g_deg + base);

    int s = 0;
    #pragma unroll
    for (int i = 0; i < 13; i++) {
        int4 d = dp[i];
        s += d.x + d.y + d.z + d.w;
    }

    int lane = tid & 31, w = tid >> 5;
    int v = s;
    #pragma unroll
    for (int o = 1; o < 32; o <<= 1) {
        int n = __shfl_up_sync(0xffffffffu, v, o);
        if (lane >= o) v += n;
    }
    if (lane == 31) wsum[w] = v;
    __syncthreads();
    if (w == 0) {
        int x = wsum[lane];
        #pragma unroll
        for (int o = 1; o < 32; o <<= 1) {
            int n = __shfl_up_sync(0xffffffffu, x, o);
            if (lane >= o) x += n;
        }
        wsum[lane] = x;
    }
    __syncthreads();
    int run = v - s + (w > 0 ? wsum[w - 1] : 0);

    int4* op = (int4*)(g_off + base);
    int4* cp = (int4*)(g_cur + base);
    int4* zp = (int4*)(g_deg + base);
    const int4 z4 = make_int4(0, 0, 0, 0);
    #pragma unroll
    for (int i = 0; i < 13; i++) {
        int4 d = dp[i];
        int4 o;
        o.x = run; run += d.x;
        o.y = run; run += d.y;
        o.z = run; run += d.z;
        o.w = run; run += d.w;
        op[i] = o;
        cp[i] = o;
        zp[i] = z4;
    }
    if (tid == 0) g_off[NN] = NE;
}

// ---------------- fused: SGEMM (raw weights, transposed in-kernel) + scatter ---
#define NB_GEMM (2 * ((NN + 127) / 128))   // 782
__global__ __launch_bounds__(256) void k_gemm_scatter(const float* __restrict__ A,
                                                      const float* __restrict__ Wr1,
                                                      const float* __restrict__ Wro1,
                                                      const int* __restrict__ ei,
                                                      const float* __restrict__ ea) {
    __shared__ float As[2][16][128];
    __shared__ float Bs[2][16][128];
    const int bid = blockIdx.x;
    const int tid = threadIdx.x;

    if (bid >= NB_GEMM) {
        // -------- scatter part --------
        int e = (bid - NB_GEMM) * 256 + tid;
        if (e < NE) {
            int d = ei[NE + e];
            int p = atomicAdd(&g_cur[d], 1);
            g_edge[p] = make_int2(ei[e], __float_as_int(ea[e]));
        }
        return;
    }

    // -------- GEMM part --------
    const int K = DIN;
    const int m0 = (bid >> 1) * 128;
    const bool relPart = ((bid & 1) == 0);
    const float* __restrict__ Wsrc = relPart ? Wr1 : Wro1;  // [n][k] row-major
    const int ty = tid >> 4, tx = tid & 15;
    const int NI = K / 16;

    const int aR0 = tid >> 2, aC0 = (tid & 3) * 4;
    // B raw-load mapping: group g = tid + 256*i covers (n = g&127, kk = (g>>7)*4)
    const int bN = tid & 127;
    const int bKq = (tid >> 7) * 4;   // 0 or 4; +8 for i=1

    float4 pa[2], pb[2];
    auto ldA = [&](int k0) {
        #pragma unroll
        for (int i = 0; i < 2; i++) {
            int gr = m0 + aR0 + i * 64;
            pa[i] = (gr < NN) ? *(const float4*)(A + (size_t)gr * K + k0 + aC0)
                              : make_float4(0.f, 0.f, 0.f, 0.f);
        }
    };
    auto ldB = [&](int k0) {
        #pragma unroll
        for (int i = 0; i < 2; i++) {
            int kk = bKq + i * 8;
            pb[i] = *(const float4*)(Wsrc + (size_t)bN * DIN + k0 + kk);
        }
    };
    auto stAB = [&](int buf) {
        #pragma unroll
        for (int i = 0; i < 2; i++) {
            int r = aR0 + i * 64;
            As[buf][aC0 + 0][r] = pa[i].x;
            As[buf][aC0 + 1][r] = pa[i].y;
            As[buf][aC0 + 2][r] = pa[i].z;
            As[buf][aC0 + 3][r] = pa[i].w;
            int kk = bKq + i * 8;
            Bs[buf][kk + 0][bN] = pb[i].x;
            Bs[buf][kk + 1][bN] = pb[i].y;
            Bs[buf][kk + 2][bN] = pb[i].z;
            Bs[buf][kk + 3][bN] = pb[i].w;
        }
    };

    float acc[8][8];
    #pragma unroll
    for (int i = 0; i < 8; i++)
        #pragma unroll
        for (int j = 0; j < 8; j++) acc[i][j] = 0.f;

    ldA(0); ldB(0);
    stAB(0);
    __syncthreads();

    int buf = 0;
    for (int it = 0; it < NI; it++) {
        if (it + 1 < NI) { ldA((it + 1) * 16); ldB((it + 1) * 16); }
        #pragma unroll
        for (int k = 0; k < 16; k++) {
            const float4 a0 = *(const float4*)&As[buf][k][ty * 8];
            const float4 a1 = *(const float4*)&As[buf][k][ty * 8 + 4];
            const float4 b0 = *(const float4*)&Bs[buf][k][tx * 8];
            const float4 b1 = *(const float4*)&Bs[buf][k][tx * 8 + 4];
            const float ar[8] = {a0.x, a0.y, a0.z, a0.w, a1.x, a1.y, a1.z, a1.w};
            const float br[8] = {b0.x, b0.y, b0.z, b0.w, b1.x, b1.y, b1.z, b1.w};
            #pragma unroll
            for (int i = 0; i < 8; i++)
                #pragma unroll
                for (int j = 0; j < 8; j++)
                    acc[i][j] = fmaf(ar[i], br[j], acc[i][j]);
        }
        if (it + 1 < NI) stAB(buf ^ 1);
        __syncthreads();
        buf ^= 1;
    }

    #pragma unroll
    for (int i = 0; i < 8; i++) {
        int r = m0 + ty * 8 + i;
        if (r >= NN) continue;
        if (relPart) {
            __half2 h0 = __floats2half2_rn(acc[i][0], acc[i][1]);
            __half2 h1 = __floats2half2_rn(acc[i][2], acc[i][3]);
            __half2 h2 = __floats2half2_rn(acc[i][4], acc[i][5]);
            __half2 h3 = __floats2half2_rn(acc[i][6], acc[i][7]);
            uint4 v;
            v.x = *(unsigned*)&h0; v.y = *(unsigned*)&h1;
            v.z = *(unsigned*)&h2; v.w = *(unsigned*)&h3;
            *(uint4*)(g_Yr16 + (size_t)r * HID + tx * 8) = v;
        } else {
            float* d0 = g_Yroot + (size_t)r * HID + tx * 8;
            *(float4*)(d0)     = make_float4(acc[i][0], acc[i][1], acc[i][2], acc[i][3]);
            *(float4*)(d0 + 4) = make_float4(acc[i][4], acc[i][5], acc[i][6], acc[i][7]);
        }
    }
}

// ---------------- layer-1 agg + u/v projection, MLP-4 batches ------------------
__device__ __forceinline__ void agg_fma(float* acc, uint4 v, float w) {
    float2 q0 = __half22float2(*(__half2*)&v.x);
    float2 q1 = __half22float2(*(__half2*)&v.y);
    float2 q2 = __half22float2(*(__half2*)&v.z);
    float2 q3 = __half22float2(*(__half2*)&v.w);
    acc[0] = fmaf(q0.x, w, acc[0]); acc[1] = fmaf(q0.y, w, acc[1]);
    acc[2] = fmaf(q1.x, w, acc[2]); acc[3] = fmaf(q1.y, w, acc[3]);
    acc[4] = fmaf(q2.x, w, acc[4]); acc[5] = fmaf(q2.y, w, acc[5]);
    acc[6] = fmaf(q3.x, w, acc[6]); acc[7] = fmaf(q3.y, w, acc[7]);
}

__global__ void k_agg1(const float* __restrict__ bias) {
    int node = (blockIdx.x * blockDim.x + threadIdx.x) >> 5;
    if (node >= NN) return;
    int lane = threadIdx.x & 31;
    int dg = lane & 15;
    int par = lane >> 4;
    int beg = g_off[node], end = g_off[node + 1];
    float acc[8] = {0.f, 0.f, 0.f, 0.f, 0.f, 0.f, 0.f, 0.f};
    int e = beg + par;
    for (; e + 6 < end; e += 8) {
        int2 ed0 = g_edge[e];
        int2 ed1 = g_edge[e + 2];
        int2 ed2 = g_edge[e + 4];
        int2 ed3 = g_edge[e + 6];
        uint4 v0 = *(const uint4*)(g_Yr16 + (size_t)ed0.x * HID + 8 * dg);
        uint4 v1 = *(const uint4*)(g_Yr16 + (size_t)ed1.x * HID + 8 * dg);
        uint4 v2 = *(const uint4*)(g_Yr16 + (size_t)ed2.x * HID + 8 * dg);
        uint4 v3 = *(const uint4*)(g_Yr16 + (size_t)ed3.x * HID + 8 * dg);
        agg_fma(acc, v0, __int_as_float(ed0.y));
        agg_fma(acc, v1, __int_as_float(ed1.y));
        agg_fma(acc, v2, __int_as_float(ed2.y));
        agg_fma(acc, v3, __int_as_float(ed3.y));
    }
    for (; e + 2 < end; e += 4) {
        int2 ed0 = g_edge[e];
        int2 ed1 = g_edge[e + 2];
        uint4 v0 = *(const uint4*)(g_Yr16 + (size_t)ed0.x * HID + 8 * dg);
        uint4 v1 = *(const uint4*)(g_Yr16 + (size_t)ed1.x * HID + 8 * dg);
        agg_fma(acc, v0, __int_as_float(ed0.y));
        agg_fma(acc, v1, __int_as_float(ed1.y));
    }
    if (e < end) {
        int2 ed0 = g_edge[e];
        uint4 v0 = *(const uint4*)(g_Yr16 + (size_t)ed0.x * HID + 8 * dg);
        agg_fma(acc, v0, __int_as_float(ed0.y));
    }
    #pragma unroll
    for (int i = 0; i < 8; i++)
        acc[i] += __shfl_xor_sync(0xffffffffu, acc[i], 16);
    int db = 8 * dg + 4 * par;
    float a0 = acc[4 * par + 0], a1 = acc[4 * par + 1];
    float a2 = acc[4 * par + 2], a3 = acc[4 * par + 3];
    float4 rt = *(const float4*)(g_Yroot + (size_t)node * HID + db);
    float4 bb = *(const float4*)(bias + db);
    float4 uu = *(const float4*)(g_u + db);
    float4 vv = *(const float4*)(g_v + db);
    float h0 = fmaxf(a0 + rt.x + bb.x, 0.f);
    float h1 = fmaxf(a1 + rt.y + bb.y, 0.f);
    float h2 = fmaxf(a2 + rt.z + bb.z, 0.f);
    float h3 = fmaxf(a3 + rt.w + bb.w, 0.f);
    float ps = h0 * uu.x + h1 * uu.y + h2 * uu.z + h3 * uu.w;
    float pr = h0 * vv.x + h1 * vv.y + h2 * vv.z + h3 * vv.w;
    #pragma unroll
    for (int o = 16; o > 0; o >>= 1) {
        ps += __shfl_down_sync(0xffffffffu, ps, o);
        pr += __shfl_down_sync(0xffffffffu, pr, o);
    }
    if (lane == 0) {
        g_s[node] = ps;
        g_r[node] = pr;
    }
}

// ---------------- fused layer-2 scalar agg + pooling + head --------------------
__global__ void k_pool2(const float* __restrict__ bl, float* __restrict__ out) {
    int g = blockIdx.x;
    int c = threadIdx.x;  // 256
    int lo = g_gs[g], l = g_gs[g + 1];
    int cnt = l - lo;
    float sum = 0.f;
    for (int i = lo + c; i < l; i += 256) {
        int beg = g_off[i], end = g_off[i + 1];
        float t = 0.f;
        int e = beg;
        for (; e + 1 < end; e += 2) {
            int2 ea = g_edge[e];
            int2 eb = g_edge[e + 1];
            float sa = g_s[ea.x];
            float sb = g_s[eb.x];
            t = fmaf(__int_as_float(ea.y), sa, t);
            t = fmaf(__int_as_float(eb.y), sb, t);
        }
        if (e < end) {
            int2 ea = g_edge[e];
            t = fmaf(__int_as_float(ea.y), g_s[ea.x], t);
        }
        sum += t + g_r[i] + g_c;
    }
    __shared__ float red[256];
    red[c] = sum;
    __syncthreads();
    for (int st = 128; st > 0; st >>= 1) {
        if (c < st) red[c] += red[c + st];
        __syncthreads();
    }
    if (c == 0) {
        float p = red[0] / fmaxf((float)cnt, 1.f);
        out[g] = fmaxf(p + bl[0], 0.f);
    }
}

// ---------------- launch (5 kernels) ----------------
extern "C" void kernel_launch(void* const* d_in, const int* in_sizes, int n_in,
                              void* d_out, int out_size) {
    const float* x     = (const float*)d_in[0];
    const int*   ei    = (const int*)d_in[1];
    const int*   batch = (const int*)d_in[2];
    const float* ea    = (const float*)d_in[3];
    const float* Wr1   = (const float*)d_in[4];
    const float* b1    = (const float*)d_in[5];
    const float* Wro1  = (const float*)d_in[6];
    const float* Wr3   = (const float*)d_in[7];
    const float* b3    = (const float*)d_in[8];
    const float* Wro3  = (const float*)d_in[9];
    const float* Wl    = (const float*)d_in[10];
    const float* bl    = (const float*)d_in[11];
    float* out = (float*)d_out;

    k_count_misc<<<NB_COUNT + 2, 256>>>(ei, batch, Wr3, Wro3, Wl, b3);
    k_scan<<<1, 1024>>>();
    k_gemm_scatter<<<NB_GEMM + NB_COUNT, 256>>>(x, Wr1, Wro1, ei, ea);
    k_agg1<<<(NN * 32 + 255) / 256, 256>>>(b1);
    k_pool2<<<NG, 256>>>(bl, out);
}

// round 15
// speedup vs baseline: 1.0595x; 1.0595x over previous
#include <cuda_runtime.h>
#include <cuda_fp16.h>

#define NN 50000
#define NE 800000
#define DIN 96
#define HID 128
#define NG 256
#define NCAT 256
#define NNP 53248   // 52 * 1024, padded arrays for vectorized scan

// ---------------- scratch ----------------
__device__ __align__(16) int    g_deg[NNP];      // zero-init; re-zeroed by k_scan
__device__ __align__(16) int    g_off[NNP + 4];
__device__ __align__(16) int    g_cur[NNP];
__device__ __align__(16) int    g_gs[NG + 1];
__device__ __align__(16) int2   g_edge[NE];
__device__ __align__(16) float  g_Wc1[DIN * NCAT];
__device__ __align__(16) __half g_Yr16[(size_t)NN * HID];
__device__ __align__(16) float  g_Yroot[(size_t)NN * HID];
__device__ __align__(16) float  g_u[HID];
__device__ __align__(16) float  g_v[HID];
__device__            float     g_c;
__device__ __align__(16) float  g_s[NN];
__device__ __align__(16) float  g_r[NN];

// ---------------- fused: degree count + weight prep + uv + graph bounds -------
#define NB_COUNT ((NE + 255) / 256)          // 3125
#define NB_WP    ((DIN * NCAT + 255) / 256)  // 96
__global__ void k_count_prep(const int* __restrict__ ei, const int* __restrict__ batch,
                             const float* __restrict__ Wr1, const float* __restrict__ Wro1,
                             const float* __restrict__ Wr3, const float* __restrict__ Wro3,
                             const float* __restrict__ Wl, const float* __restrict__ b3) {
    int b = blockIdx.x;
    if (b < NB_COUNT) {
        int e = b * 256 + threadIdx.x;
        if (e < NE) atomicAdd(&g_deg[ei[NE + e]], 1);
    } else if (b < NB_COUNT + NB_WP) {
        int idx = (b - NB_COUNT) * 256 + threadIdx.x;
        if (idx < DIN * NCAT) {
            int k = idx / NCAT, j = idx % NCAT;
            g_Wc1[idx] = (j < HID) ? Wr1[j * DIN + k] : Wro1[(j - HID) * DIN + k];
        }
    } else if (b == NB_COUNT + NB_WP) {
        int k = threadIdx.x;
        if (k < HID) {
            float su = 0.f, sv = 0.f;
            #pragma unroll 4
            for (int j = 0; j < HID; j++) {
                float wl = Wl[j];
                su = fmaf(wl, Wr3[j * HID + k], su);
                sv = fmaf(wl, Wro3[j * HID + k], sv);
            }
            g_u[k] = su;
            g_v[k] = sv;
            if (k == 0) {
                float c = 0.f;
                for (int j = 0; j < HID; j++) c = fmaf(Wl[j], b3[j], c);
                g_c = c;
            }
        }
    } else {
        int g = threadIdx.x;  // 0..255
        int lo = 0, hi = NN;
        while (lo < hi) {
            int m = (lo + hi) >> 1;
            if (batch[m] < g) lo = m + 1; else hi = m;
        }
        g_gs[g] = lo;
        if (g == 0) g_gs[NG] = NN;
    }
}

// ---------------- scan: vectorized, two-pass ----------------
__global__ __launch_bounds__(1024) void k_scan() {
    __shared__ int wsum[32];
    const int tid = threadIdx.x;
    const int base = tid * 52;
    const int4* dp = (const int4*)(g_deg + base);

    int s = 0;
    #pragma unroll
    for (int i = 0; i < 13; i++) {
        int4 d = dp[i];
        s += d.x + d.y + d.z + d.w;
    }

    int lane = tid & 31, w = tid >> 5;
    int v = s;
    #pragma unroll
    for (int o = 1; o < 32; o <<= 1) {
        int n = __shfl_up_sync(0xffffffffu, v, o);
        if (lane >= o) v += n;
    }
    if (lane == 31) wsum[w] = v;
    __syncthreads();
    if (w == 0) {
        int x = wsum[lane];
        #pragma unroll
        for (int o = 1; o < 32; o <<= 1) {
            int n = __shfl_up_sync(0xffffffffu, x, o);
            if (lane >= o) x += n;
        }
        wsum[lane] = x;
    }
    __syncthreads();
    int run = v - s + (w > 0 ? wsum[w - 1] : 0);

    int4* op = (int4*)(g_off + base);
    int4* cp = (int4*)(g_cur + base);
    int4* zp = (int4*)(g_deg + base);
    const int4 z4 = make_int4(0, 0, 0, 0);
    #pragma unroll
    for (int i = 0; i < 13; i++) {
        int4 d = dp[i];
        int4 o;
        o.x = run; run += d.x;
        o.y = run; run += d.y;
        o.z = run; run += d.z;
        o.w = run; run += d.w;
        op[i] = o;
        cp[i] = o;
        zp[i] = z4;
    }
    if (tid == 0) g_off[NN] = NE;
}

// ---------------- fused: SGEMM (blocks 0..781) + scatter (rest) ---------------
#define NB_GEMM (2 * ((NN + 127) / 128))   // 782
__global__ __launch_bounds__(256) void k_gemm_scatter(const float* __restrict__ A,
                                                      const int* __restrict__ ei,
                                                      const float* __restrict__ ea) {
    __shared__ float As[2][16][128];
    __shared__ float Bs[2][16][128];
    const int bid = blockIdx.x;
    const int tid = threadIdx.x;

    if (bid >= NB_GEMM) {
        int e = (bid - NB_GEMM) * 256 + tid;
        if (e < NE) {
            int d = ei[NE + e];
            int p = atomicAdd(&g_cur[d], 1);
            g_edge[p] = make_int2(ei[e], __float_as_int(ea[e]));
        }
        return;
    }

    const int K = DIN;
    const float* __restrict__ B = g_Wc1;
    const int m0 = (bid >> 1) * 128;
    const int n0 = (bid & 1) * 128;
    const int ty = tid >> 4, tx = tid & 15;
    const int NI = K / 16;

    const int aR0 = tid >> 2, aC0 = (tid & 3) * 4;
    const int bK0 = tid >> 5, bN0 = (tid & 31) * 4;

    float4 pa[2], pb[2];
    auto ldA = [&](int k0) {
        #pragma unroll
        for (int i = 0; i < 2; i++) {
            int gr = m0 + aR0 + i * 64;
            pa[i] = (gr < NN) ? *(const float4*)(A + (size_t)gr * K + k0 + aC0)
                              : make_float4(0.f, 0.f, 0.f, 0.f);
        }
    };
    auto ldB = [&](int k0) {
        #pragma unroll
        for (int i = 0; i < 2; i++) {
            int kk = bK0 + i * 8;
            pb[i] = *(const float4*)(B + (size_t)(k0 + kk) * NCAT + n0 + bN0);
        }
    };
    auto stAB = [&](int buf) {
        #pragma unroll
        for (int i = 0; i < 2; i++) {
            int r = aR0 + i * 64;
            As[buf][aC0 + 0][r] = pa[i].x;
            As[buf][aC0 + 1][r] = pa[i].y;
            As[buf][aC0 + 2][r] = pa[i].z;
            As[buf][aC0 + 3][r] = pa[i].w;
            *(float4*)&Bs[buf][bK0 + i * 8][bN0] = pb[i];
        }
    };

    float acc[8][8];
    #pragma unroll
    for (int i = 0; i < 8; i++)
        #pragma unroll
        for (int j = 0; j < 8; j++) acc[i][j] = 0.f;

    ldA(0); ldB(0);
    stAB(0);
    __syncthreads();

    int buf = 0;
    for (int it = 0; it < NI; it++) {
        if (it + 1 < NI) { ldA((it + 1) * 16); ldB((it + 1) * 16); }
        #pragma unroll
        for (int k = 0; k < 16; k++) {
            const float4 a0 = *(const float4*)&As[buf][k][ty * 8];
            const float4 a1 = *(const float4*)&As[buf][k][ty * 8 + 4];
            const float4 b0 = *(const float4*)&Bs[buf][k][tx * 8];
            const float4 b1 = *(const float4*)&Bs[buf][k][tx * 8 + 4];
            const float ar[8] = {a0.x, a0.y, a0.z, a0.w, a1.x, a1.y, a1.z, a1.w};
            const float br[8] = {b0.x, b0.y, b0.z, b0.w, b1.x, b1.y, b1.z, b1.w};
            #pragma unroll
            for (int i = 0; i < 8; i++)
                #pragma unroll
                for (int j = 0; j < 8; j++)
                    acc[i][j] = fmaf(ar[i], br[j], acc[i][j]);
        }
        if (it + 1 < NI) stAB(buf ^ 1);
        __syncthreads();
        buf ^= 1;
    }

    const bool relPart = ((bid & 1) == 0);
    #pragma unroll
    for (int i = 0; i < 8; i++) {
        int r = m0 + ty * 8 + i;
        if (r >= NN) continue;
        if (relPart) {
            __half2 h0 = __floats2half2_rn(acc[i][0], acc[i][1]);
            __half2 h1 = __floats2half2_rn(acc[i][2], acc[i][3]);
            __half2 h2 = __floats2half2_rn(acc[i][4], acc[i][5]);
            __half2 h3 = __floats2half2_rn(acc[i][6], acc[i][7]);
            uint4 v;
            v.x = *(unsigned*)&h0; v.y = *(unsigned*)&h1;
            v.z = *(unsigned*)&h2; v.w = *(unsigned*)&h3;
            *(uint4*)(g_Yr16 + (size_t)r * HID + tx * 8) = v;
        } else {
            float* d0 = g_Yroot + (size_t)r * HID + tx * 8;
            *(float4*)(d0)     = make_float4(acc[i][0], acc[i][1], acc[i][2], acc[i][3]);
            *(float4*)(d0 + 4) = make_float4(acc[i][4], acc[i][5], acc[i][6], acc[i][7]);
        }
    }
}

// ---------------- layer-1 agg + u/v projection, MLP-8 batches ------------------
__device__ __forceinline__ void agg_fma(float* acc, uint4 v, float w) {
    float2 q0 = __half22float2(*(__half2*)&v.x);
    float2 q1 = __half22float2(*(__half2*)&v.y);
    float2 q2 = __half22float2(*(__half2*)&v.z);
    float2 q3 = __half22float2(*(__half2*)&v.w);
    acc[0] = fmaf(q0.x, w, acc[0]); acc[1] = fmaf(q0.y, w, acc[1]);
    acc[2] = fmaf(q1.x, w, acc[2]); acc[3] = fmaf(q1.y, w, acc[3]);
    acc[4] = fmaf(q2.x, w, acc[4]); acc[5] = fmaf(q2.y, w, acc[5]);
    acc[6] = fmaf(q3.x, w, acc[6]); acc[7] = fmaf(q3.y, w, acc[7]);
}

__global__ void k_agg1(const float* __restrict__ bias) {
    int node = (blockIdx.x * blockDim.x + threadIdx.x) >> 5;
    if (node >= NN) return;
    int lane = threadIdx.x & 31;
    int dg = lane & 15;
    int par = lane >> 4;
    int beg = g_off[node], end = g_off[node + 1];
    float acc[8] = {0.f, 0.f, 0.f, 0.f, 0.f, 0.f, 0.f, 0.f};
    int e = beg + par;
    // 8 edges per parity in flight (MLP=8)
    for (; e + 14 < end; e += 16) {
        int2 ed[8];
        uint4 v[8];
        #pragma unroll
        for (int q = 0; q < 8; q++) ed[q] = g_edge[e + 2 * q];
        #pragma unroll
        for (int q = 0; q < 8; q++)
            v[q] = *(const uint4*)(g_Yr16 + (size_t)ed[q].x * HID + 8 * dg);
        #pragma unroll
        for (int q = 0; q < 8; q++) agg_fma(acc, v[q], __int_as_float(ed[q].y));
    }
    for (; e + 2 < end; e += 4) {
        int2 ed0 = g_edge[e];
        int2 ed1 = g_edge[e + 2];
        uint4 v0 = *(const uint4*)(g_Yr16 + (size_t)ed0.x * HID + 8 * dg);
        uint4 v1 = *(const uint4*)(g_Yr16 + (size_t)ed1.x * HID + 8 * dg);
        agg_fma(acc, v0, __int_as_float(ed0.y));
        agg_fma(acc, v1, __int_as_float(ed1.y));
    }
    if (e < end) {
        int2 ed0 = g_edge[e];
        uint4 v0 = *(const uint4*)(g_Yr16 + (size_t)ed0.x * HID + 8 * dg);
        agg_fma(acc, v0, __int_as_float(ed0.y));
    }
    #pragma unroll
    for (int i = 0; i < 8; i++)
        acc[i] += __shfl_xor_sync(0xffffffffu, acc[i], 16);
    int db = 8 * dg + 4 * par;
    float a0 = acc[4 * par + 0], a1 = acc[4 * par + 1];
    float a2 = acc[4 * par + 2], a3 = acc[4 * par + 3];
    float4 rt = *(const float4*)(g_Yroot + (size_t)node * HID + db);
    float4 bb = *(const float4*)(bias + db);
    float4 uu = *(const float4*)(g_u + db);
    float4 vv = *(const float4*)(g_v + db);
    float h0 = fmaxf(a0 + rt.x + bb.x, 0.f);
    float h1 = fmaxf(a1 + rt.y + bb.y, 0.f);
    float h2 = fmaxf(a2 + rt.z + bb.z, 0.f);
    float h3 = fmaxf(a3 + rt.w + bb.w, 0.f);
    float ps = h0 * uu.x + h1 * uu.y + h2 * uu.z + h3 * uu.w;
    float pr = h0 * vv.x + h1 * vv.y + h2 * vv.z + h3 * vv.w;
    #pragma unroll
    for (int o = 16; o > 0; o >>= 1) {
        ps += __shfl_down_sync(0xffffffffu, ps, o);
        pr += __shfl_down_sync(0xffffffffu, pr, o);
    }
    if (lane == 0) {
        g_s[node] = ps;
        g_r[node] = pr;
    }
}

// ---------------- fused layer-2 scalar agg + pooling + head --------------------
__global__ void k_pool2(const float* __restrict__ bl, float* __restrict__ out) {
    int g = blockIdx.x;
    int c = threadIdx.x;  // 256
    int lo = g_gs[g], l = g_gs[g + 1];
    int cnt = l - lo;
    float sum = 0.f;
    for (int i = lo + c; i < l; i += 256) {
        int beg = g_off[i], end = g_off[i + 1];
        float t = 0.f;
        int e = beg;
        // MLP-4 batches
        for (; e + 3 < end; e += 4) {
            int2 e0 = g_edge[e];
            int2 e1 = g_edge[e + 1];
            int2 e2 = g_edge[e + 2];
            int2 e3 = g_edge[e + 3];
            float s0 = g_s[e0.x];
            float s1 = g_s[e1.x];
            float s2 = g_s[e2.x];
            float s3 = g_s[e3.x];
            t = fmaf(__int_as_float(e0.y), s0, t);
            t = fmaf(__int_as_float(e1.y), s1, t);
            t = fmaf(__int_as_float(e2.y), s2, t);
            t = fmaf(__int_as_float(e3.y), s3, t);
        }
        for (; e < end; e++) {
            int2 ea = g_edge[e];
            t = fmaf(__int_as_float(ea.y), g_s[ea.x], t);
        }
        sum += t + g_r[i] + g_c;
    }
    __shared__ float red[256];
    red[c] = sum;
    __syncthreads();
    for (int st = 128; st > 0; st >>= 1) {
        if (c < st) red[c] += red[c + st];
        __syncthreads();
    }
    if (c == 0) {
        float p = red[0] / fmaxf((float)cnt, 1.f);
        out[g] = fmaxf(p + bl[0], 0.f);
    }
}

// ---------------- launch (5 kernels) ----------------
extern "C" void kernel_launch(void* const* d_in, const int* in_sizes, int n_in,
                              void* d_out, int out_size) {
    const float* x     = (const float*)d_in[0];
    const int*   ei    = (const int*)d_in[1];
    const int*   batch = (const int*)d_in[2];
    const float* ea    = (const float*)d_in[3];
    const float* Wr1   = (const float*)d_in[4];
    const float* b1    = (const float*)d_in[5];
    const float* Wro1  = (const float*)d_in[6];
    const float* Wr3   = (const float*)d_in[7];
    const float* b3    = (const float*)d_in[8];
    const float* Wro3  = (const float*)d_in[9];
    const float* Wl    = (const float*)d_in[10];
    const float* bl    = (const float*)d_in[11];
    float* out = (float*)d_out;

    k_count_prep<<<NB_COUNT + NB_WP + 2, 256>>>(ei, batch, Wr1, Wro1, Wr3, Wro3, Wl, b3);
    k_scan<<<1, 1024>>>();
    k_gemm_scatter<<<NB_GEMM + NB_COUNT, 256>>>(x, ei, ea);
    k_agg1<<<(NN * 32 + 255) / 256, 256>>>(b1);
    k_pool2<<<NG, 256>>>(bl, out);
}

// round 16
// speedup vs baseline: 1.1017x; 1.0398x over previous
#include <cuda_runtime.h>
#include <cuda_fp16.h>

#define NN 50000
#define NE 800000
#define DIN 96
#define HID 128
#define NG 256
#define NCAT 256
#define NNP 53248   // 52 * 1024, padded arrays for vectorized scan

// ---------------- scratch ----------------
__device__ __align__(16) int    g_deg[NNP];      // zero-init; re-zeroed by k_scan
__device__ __align__(16) int    g_off[NNP + 4];
__device__ __align__(16) int    g_cur[NNP];
__device__ __align__(16) int    g_gs[NG + 1];
__device__ __align__(16) int2   g_edge[NE];
__device__ __align__(16) float  g_Wc1[DIN * NCAT];
__device__ __align__(16) __half g_Yr16[(size_t)NN * HID];    // rel half (gathered)
__device__ __align__(16) __half g_Yroot16[(size_t)NN * HID]; // root half (fp16 now)
__device__ __align__(16) float  g_u[HID];
__device__ __align__(16) float  g_v[HID];
__device__            float     g_c;
__device__ __align__(16) float  g_s[NN];
__device__ __align__(16) float  g_r[NN];

// ---------------- fused: degree count + weight prep + uv + graph bounds -------
#define NB_COUNT ((NE + 255) / 256)          // 3125
#define NB_WP    ((DIN * NCAT + 255) / 256)  // 96
__global__ void k_count_prep(const int* __restrict__ ei, const int* __restrict__ batch,
                             const float* __restrict__ Wr1, const float* __restrict__ Wro1,
                             const float* __restrict__ Wr3, const float* __restrict__ Wro3,
                             const float* __restrict__ Wl, const float* __restrict__ b3) {
    int b = blockIdx.x;
    if (b < NB_COUNT) {
        int e = b * 256 + threadIdx.x;
        if (e < NE) atomicAdd(&g_deg[ei[NE + e]], 1);
    } else if (b < NB_COUNT + NB_WP) {
        int idx = (b - NB_COUNT) * 256 + threadIdx.x;
        if (idx < DIN * NCAT) {
            int k = idx / NCAT, j = idx % NCAT;
            g_Wc1[idx] = (j < HID) ? Wr1[j * DIN + k] : Wro1[(j - HID) * DIN + k];
        }
    } else if (b == NB_COUNT + NB_WP) {
        int k = threadIdx.x;
        if (k < HID) {
            float su = 0.f, sv = 0.f;
            #pragma unroll 4
            for (int j = 0; j < HID; j++) {
                float wl = Wl[j];
                su = fmaf(wl, Wr3[j * HID + k], su);
                sv = fmaf(wl, Wro3[j * HID + k], sv);
            }
            g_u[k] = su;
            g_v[k] = sv;
            if (k == 0) {
                float c = 0.f;
                for (int j = 0; j < HID; j++) c = fmaf(Wl[j], b3[j], c);
                g_c = c;
            }
        }
    } else {
        int g = threadIdx.x;  // 0..255
        int lo = 0, hi = NN;
        while (lo < hi) {
            int m = (lo + hi) >> 1;
            if (batch[m] < g) lo = m + 1; else hi = m;
        }
        g_gs[g] = lo;
        if (g == 0) g_gs[NG] = NN;
    }
}

// ---------------- scan: vectorized, two-pass ----------------
__global__ __launch_bounds__(1024) void k_scan() {
    __shared__ int wsum[32];
    const int tid = threadIdx.x;
    const int base = tid * 52;
    const int4* dp = (const int4*)(g_deg + base);

    int s = 0;
    #pragma unroll
    for (int i = 0; i < 13; i++) {
        int4 d = dp[i];
        s += d.x + d.y + d.z + d.w;
    }

    int lane = tid & 31, w = tid >> 5;
    int v = s;
    #pragma unroll
    for (int o = 1; o < 32; o <<= 1) {
        int n = __shfl_up_sync(0xffffffffu, v, o);
        if (lane >= o) v += n;
    }
    if (lane == 31) wsum[w] = v;
    __syncthreads();
    if (w == 0) {
        int x = wsum[lane];
        #pragma unroll
        for (int o = 1; o < 32; o <<= 1) {
            int n = __shfl_up_sync(0xffffffffu, x, o);
            if (lane >= o) x += n;
        }
        wsum[lane] = x;
    }
    __syncthreads();
    int run = v - s + (w > 0 ? wsum[w - 1] : 0);

    int4* op = (int4*)(g_off + base);
    int4* cp = (int4*)(g_cur + base);
    int4* zp = (int4*)(g_deg + base);
    const int4 z4 = make_int4(0, 0, 0, 0);
    #pragma unroll
    for (int i = 0; i < 13; i++) {
        int4 d = dp[i];
        int4 o;
        o.x = run; run += d.x;
        o.y = run; run += d.y;
        o.z = run; run += d.z;
        o.w = run; run += d.w;
        op[i] = o;
        cp[i] = o;
        zp[i] = z4;
    }
    if (tid == 0) g_off[NN] = NE;
}

// ---------------- fused: SGEMM (blocks 0..781) + scatter (rest) ---------------
#define NB_GEMM (2 * ((NN + 127) / 128))   // 782
__global__ __launch_bounds__(256) void k_gemm_scatter(const float* __restrict__ A,
                                                      const int* __restrict__ ei,
                                                      const float* __restrict__ ea) {
    __shared__ float As[2][16][128];
    __shared__ float Bs[2][16][128];
    const int bid = blockIdx.x;
    const int tid = threadIdx.x;

    if (bid >= NB_GEMM) {
        int e = (bid - NB_GEMM) * 256 + tid;
        if (e < NE) {
            int d = ei[NE + e];
            int p = atomicAdd(&g_cur[d], 1);
            g_edge[p] = make_int2(ei[e], __float_as_int(ea[e]));
        }
        return;
    }

    const int K = DIN;
    const float* __restrict__ B = g_Wc1;
    const int m0 = (bid >> 1) * 128;
    const int n0 = (bid & 1) * 128;
    const int ty = tid >> 4, tx = tid & 15;
    const int NI = K / 16;

    const int aR0 = tid >> 2, aC0 = (tid & 3) * 4;
    const int bK0 = tid >> 5, bN0 = (tid & 31) * 4;

    float4 pa[2], pb[2];
    auto ldA = [&](int k0) {
        #pragma unroll
        for (int i = 0; i < 2; i++) {
            int gr = m0 + aR0 + i * 64;
            pa[i] = (gr < NN) ? *(const float4*)(A + (size_t)gr * K + k0 + aC0)
                              : make_float4(0.f, 0.f, 0.f, 0.f);
        }
    };
    auto ldB = [&](int k0) {
        #pragma unroll
        for (int i = 0; i < 2; i++) {
            int kk = bK0 + i * 8;
            pb[i] = *(const float4*)(B + (size_t)(k0 + kk) * NCAT + n0 + bN0);
        }
    };
    auto stAB = [&](int buf) {
        #pragma unroll
        for (int i = 0; i < 2; i++) {
            int r = aR0 + i * 64;
            As[buf][aC0 + 0][r] = pa[i].x;
            As[buf][aC0 + 1][r] = pa[i].y;
            As[buf][aC0 + 2][r] = pa[i].z;
            As[buf][aC0 + 3][r] = pa[i].w;
            *(float4*)&Bs[buf][bK0 + i * 8][bN0] = pb[i];
        }
    };

    float acc[8][8];
    #pragma unroll
    for (int i = 0; i < 8; i++)
        #pragma unroll
        for (int j = 0; j < 8; j++) acc[i][j] = 0.f;

    ldA(0); ldB(0);
    stAB(0);
    __syncthreads();

    int buf = 0;
    for (int it = 0; it < NI; it++) {
        if (it + 1 < NI) { ldA((it + 1) * 16); ldB((it + 1) * 16); }
        #pragma unroll
        for (int k = 0; k < 16; k++) {
            const float4 a0 = *(const float4*)&As[buf][k][ty * 8];
            const float4 a1 = *(const float4*)&As[buf][k][ty * 8 + 4];
            const float4 b0 = *(const float4*)&Bs[buf][k][tx * 8];
            const float4 b1 = *(const float4*)&Bs[buf][k][tx * 8 + 4];
            const float ar[8] = {a0.x, a0.y, a0.z, a0.w, a1.x, a1.y, a1.z, a1.w};
            const float br[8] = {b0.x, b0.y, b0.z, b0.w, b1.x, b1.y, b1.z, b1.w};
            #pragma unroll
            for (int i = 0; i < 8; i++)
                #pragma unroll
                for (int j = 0; j < 8; j++)
                    acc[i][j] = fmaf(ar[i], br[j], acc[i][j]);
        }
        if (it + 1 < NI) stAB(buf ^ 1);
        __syncthreads();
        buf ^= 1;
    }

    // epilogue: both halves stored as fp16 (rel -> g_Yr16, root -> g_Yroot16)
    __half* __restrict__ dstBase = ((bid & 1) == 0) ? g_Yr16 : g_Yroot16;
    #pragma unroll
    for (int i = 0; i < 8; i++) {
        int r = m0 + ty * 8 + i;
        if (r >= NN) continue;
        __half2 h0 = __floats2half2_rn(acc[i][0], acc[i][1]);
        __half2 h1 = __floats2half2_rn(acc[i][2], acc[i][3]);
        __half2 h2 = __floats2half2_rn(acc[i][4], acc[i][5]);
        __half2 h3 = __floats2half2_rn(acc[i][6], acc[i][7]);
        uint4 v;
        v.x = *(unsigned*)&h0; v.y = *(unsigned*)&h1;
        v.z = *(unsigned*)&h2; v.w = *(unsigned*)&h3;
        *(uint4*)(dstBase + (size_t)r * HID + tx * 8) = v;
    }
}

// ---------------- layer-1 agg + u/v projection, MLP-8 batches ------------------
__device__ __forceinline__ void agg_fma(float* acc, uint4 v, float w) {
    float2 q0 = __half22float2(*(__half2*)&v.x);
    float2 q1 = __half22float2(*(__half2*)&v.y);
    float2 q2 = __half22float2(*(__half2*)&v.z);
    float2 q3 = __half22float2(*(__half2*)&v.w);
    acc[0] = fmaf(q0.x, w, acc[0]); acc[1] = fmaf(q0.y, w, acc[1]);
    acc[2] = fmaf(q1.x, w, acc[2]); acc[3] = fmaf(q1.y, w, acc[3]);
    acc[4] = fmaf(q2.x, w, acc[4]); acc[5] = fmaf(q2.y, w, acc[5]);
    acc[6] = fmaf(q3.x, w, acc[6]); acc[7] = fmaf(q3.y, w, acc[7]);
}

__global__ void k_agg1(const float* __restrict__ bias) {
    int node = (blockIdx.x * blockDim.x + threadIdx.x) >> 5;
    if (node >= NN) return;
    int lane = threadIdx.x & 31;
    int dg = lane & 15;
    int par = lane >> 4;
    int beg = g_off[node], end = g_off[node + 1];
    float acc[8] = {0.f, 0.f, 0.f, 0.f, 0.f, 0.f, 0.f, 0.f};
    int e = beg + par;
    for (; e + 14 < end; e += 16) {
        int2 ed[8];
        uint4 v[8];
        #pragma unroll
        for (int q = 0; q < 8; q++) ed[q] = g_edge[e + 2 * q];
        #pragma unroll
        for (int q = 0; q < 8; q++)
            v[q] = *(const uint4*)(g_Yr16 + (size_t)ed[q].x * HID + 8 * dg);
        #pragma unroll
        for (int q = 0; q < 8; q++) agg_fma(acc, v[q], __int_as_float(ed[q].y));
    }
    for (; e + 2 < end; e += 4) {
        int2 ed0 = g_edge[e];
        int2 ed1 = g_edge[e + 2];
        uint4 v0 = *(const uint4*)(g_Yr16 + (size_t)ed0.x * HID + 8 * dg);
        uint4 v1 = *(const uint4*)(g_Yr16 + (size_t)ed1.x * HID + 8 * dg);
        agg_fma(acc, v0, __int_as_float(ed0.y));
        agg_fma(acc, v1, __int_as_float(ed1.y));
    }
    if (e < end) {
        int2 ed0 = g_edge[e];
        uint4 v0 = *(const uint4*)(g_Yr16 + (size_t)ed0.x * HID + 8 * dg);
        agg_fma(acc, v0, __int_as_float(ed0.y));
    }
    #pragma unroll
    for (int i = 0; i < 8; i++)
        acc[i] += __shfl_xor_sync(0xffffffffu, acc[i], 16);
    int db = 8 * dg + 4 * par;
    float a0 = acc[4 * par + 0], a1 = acc[4 * par + 1];
    float a2 = acc[4 * par + 2], a3 = acc[4 * par + 3];
    // root half (fp16) + bias + u/v
    uint2 rtx = *(const uint2*)(g_Yroot16 + (size_t)node * HID + db);
    float2 r01 = __half22float2(*(__half2*)&rtx.x);
    float2 r23 = __half22float2(*(__half2*)&rtx.y);
    float4 bb = *(const float4*)(bias + db);
    float4 uu = *(const float4*)(g_u + db);
    float4 vv = *(const float4*)(g_v + db);
    float h0 = fmaxf(a0 + r01.x + bb.x, 0.f);
    float h1 = fmaxf(a1 + r01.y + bb.y, 0.f);
    float h2 = fmaxf(a2 + r23.x + bb.z, 0.f);
    float h3 = fmaxf(a3 + r23.y + bb.w, 0.f);
    float ps = h0 * uu.x + h1 * uu.y + h2 * uu.z + h3 * uu.w;
    float pr = h0 * vv.x + h1 * vv.y + h2 * vv.z + h3 * vv.w;
    #pragma unroll
    for (int o = 16; o > 0; o >>= 1) {
        ps += __shfl_down_sync(0xffffffffu, ps, o);
        pr += __shfl_down_sync(0xffffffffu, pr, o);
    }
    if (lane == 0) {
        g_s[node] = ps;
        g_r[node] = pr;
    }
}

// ---------------- pooling: per-graph contiguous edge-range streaming -----------
// sum_g z = sum_{e: dst in g} w*s[src] + sum_{i in g} r_i + cnt*c
// (edges are CSR-sorted by dst; batch sorted -> each graph owns edge range)
__global__ void k_pool2(const float* __restrict__ bl, float* __restrict__ out) {
    int g = blockIdx.x;
    int c = threadIdx.x;  // 256
    int nlo = g_gs[g], nhi = g_gs[g + 1];
    int cnt = nhi - nlo;
    int elo = g_off[nlo], ehi = g_off[nhi];
    float sum = 0.f;
    // edge part: coalesced stream with 4-way batching
    int e = elo + c;
    for (; e + 3 * 256 < ehi; e += 4 * 256) {
        int2 e0 = g_edge[e];
        int2 e1 = g_edge[e + 256];
        int2 e2 = g_edge[e + 512];
        int2 e3 = g_edge[e + 768];
        float s0 = g_s[e0.x];
        float s1 = g_s[e1.x];
        float s2 = g_s[e2.x];
        float s3 = g_s[e3.x];
        sum = fmaf(__int_as_float(e0.y), s0, sum);
        sum = fmaf(__int_as_float(e1.y), s1, sum);
        sum = fmaf(__int_as_float(e2.y), s2, sum);
        sum = fmaf(__int_as_float(e3.y), s3, sum);
    }
    for (; e < ehi; e += 256) {
        int2 ed = g_edge[e];
        sum = fmaf(__int_as_float(ed.y), g_s[ed.x], sum);
    }
    // node part: r_i
    for (int i = nlo + c; i < nhi; i += 256) sum += g_r[i];

    __shared__ float red[256];
    red[c] = sum;
    __syncthreads();
    for (int st = 128; st > 0; st >>= 1) {
        if (c < st) red[c] += red[c + st];
        __syncthreads();
    }
    if (c == 0) {
        float tot = red[0] + (float)cnt * g_c;
        float p = tot / fmaxf((float)cnt, 1.f);
        out[g] = fmaxf(p + bl[0], 0.f);
    }
}

// ---------------- launch (5 kernels) ----------------
extern "C" void kernel_launch(void* const* d_in, const int* in_sizes, int n_in,
                              void* d_out, int out_size) {
    const float* x     = (const float*)d_in[0];
    const int*   ei    = (const int*)d_in[1];
    const int*   batch = (const int*)d_in[2];
    const float* ea    = (const float*)d_in[3];
    const float* Wr1   = (const float*)d_in[4];
    const float* b1    = (const float*)d_in[5];
    const float* Wro1  = (const float*)d_in[6];
    const float* Wr3   = (const float*)d_in[7];
    const float* b3    = (const float*)d_in[8];
    const float* Wro3  = (const float*)d_in[9];
    const float* Wl    = (const float*)d_in[10];
    const float* bl    = (const float*)d_in[11];
    float* out = (float*)d_out;

    k_count_prep<<<NB_COUNT + NB_WP + 2, 256>>>(ei, batch, Wr1, Wro1, Wr3, Wro3, Wl, b3);
    k_scan<<<1, 1024>>>();
    k_gemm_scatter<<<NB_GEMM + NB_COUNT, 256>>>(x, ei, ea);
    k_agg1<<<(NN * 32 + 255) / 256, 256>>>(b1);
    k_pool2<<<NG, 256>>>(bl, out);
}